// round 16
// baseline (speedup 1.0000x reference)
#include <cuda_runtime.h>
#include <cuda_fp16.h>
#include <stdint.h>
#include <math.h>

// Problem constants
constexpr int Bc   = 16;
constexpr int Nn   = 20000;
constexpr int Cc   = 64;
constexpr int Ee   = 640000;
constexpr int NBlk = 3;
constexpr int ROWS = Nn * Bc;          // 320000
constexpr int RowF = Bc * Cc;          // 1024 halfs per node row ([N][B][C])
constexpr int RowF4 = RowF / 4;
constexpr int NSCAN = (Nn + 255) / 256;  // 79 scan blocks

// -------- device scratch --------
__device__ __align__(16) float  g_h  [ROWS * Cc];
__device__ __align__(16) __half g_hh [ROWS * Cc];
__device__ __align__(16) __half g_t1h[ROWS * Cc];
__device__ __align__(16) __half g_t2h[ROWS * Cc];
__device__ float g_deg [Nn];
__device__ int   g_off [Nn + 1];
__device__ int   g_cnt [Nn];
__device__ int   g_bsum[NSCAN];
__device__ int   g_bbase[NSCAN + 1];
__device__ int   g_csrc[Ee];
__device__ float g_csw [Ee];
// Pre-packed fp16 B operands (hi only), LANE-VECTORIZED fragment layout:
// N=128: word r = k2*128 + gq*16 + wn*4 + ni  (n = wn*32 + ni*8 + gq)
// N=64 : word r = k2*64  + gq*8  + wn*2 + ni  (n = wn*16 + ni*8 + gq)
__device__ __align__(16) uint32_t g_Bc[3][3][32 * 128];   // [block][chunk]
__device__ __align__(16) uint32_t g_B1[3][2][32 * 128];
__device__ __align__(16) uint32_t g_B2[3][2][32 * 64];

// -------- setup kernels --------
__global__ void zero_deg_cnt() {
    int i = blockIdx.x * blockDim.x + threadIdx.x;
    if (i < Nn) { g_deg[i] = 0.f; g_cnt[i] = 0; }
}
// degree accumulate + dst count in one E-pass
__global__ void deg_cnt_kernel(const int* __restrict__ src, const int* __restrict__ dst,
                               const float* __restrict__ ew) {
    int e = blockIdx.x * blockDim.x + threadIdx.x;
    if (e < Ee) {
        atomicAdd(&g_deg[src[e]], ew[e]);
        atomicAdd(&g_cnt[dst[e]], 1);
    }
}
__global__ void scan1_kernel() {
    __shared__ int wsum[8];
    int b = blockIdx.x, t = threadIdx.x;
    int i = b * 256 + t;
    int v = (i < Nn) ? g_cnt[i] : 0;
    if (i < Nn) g_cnt[i] = 0;
    int x = v;
    #pragma unroll
    for (int d = 1; d < 32; d <<= 1) {
        int y = __shfl_up_sync(0xFFFFFFFFu, x, d);
        if ((t & 31) >= d) x += y;
    }
    if ((t & 31) == 31) wsum[t >> 5] = x;
    __syncthreads();
    if (t < 8) {
        int y = wsum[t];
        #pragma unroll
        for (int d = 1; d < 8; d <<= 1) {
            int z = __shfl_up_sync(0xFFu, y, d);
            if (t >= d) y += z;
        }
        wsum[t] = y;
    }
    __syncthreads();
    int excl = (x - v) + ((t >= 32) ? wsum[(t >> 5) - 1] : 0);
    if (i < Nn) g_off[i] = excl;
    if (t == 255) g_bsum[b] = excl + v;
}
__global__ void scan2_kernel() {
    int t = threadIdx.x;
    __shared__ int sh[NSCAN];
    if (t < NSCAN) sh[t] = g_bsum[t];
    __syncthreads();
    if (t == 0) {
        int run = 0;
        #pragma unroll 4
        for (int b = 0; b < NSCAN; ++b) { g_bbase[b] = run; run += sh[b]; }
        g_bbase[NSCAN] = run;
        g_off[Nn] = run;
    }
}
__global__ void scan3_kernel() {
    int i = blockIdx.x * 256 + threadIdx.x;
    if (i < Nn) g_off[i] += g_bbase[blockIdx.x];
}
// fill with inline normalized-weight computation (w_count pass folded in)
__global__ void fill_kernel(const int* __restrict__ src, const int* __restrict__ dst,
                            const float* __restrict__ ew) {
    int e = blockIdx.x * blockDim.x + threadIdx.x;
    if (e < Ee) {
        int s = src[e], d = dst[e];
        float ds = g_deg[s], dd = g_deg[d];
        float is = (ds > 0.f) ? rsqrtf(fmaxf(ds, 1e-12f)) : 0.f;
        float id = (dd > 0.f) ? rsqrtf(fmaxf(dd, 1e-12f)) : 0.f;
        int pos = g_off[d] + atomicAdd(&g_cnt[d], 1);
        g_csrc[pos] = s;
        g_csw[pos]  = -is * ew[e] * id;
    }
}

// -------- input transpose: fp16 shadow only (g_h materialized by fused block 0) --------
__global__ void t_in_kernel(const float4* __restrict__ x4) {
    int idx = blockIdx.x * 256 + threadIdx.x;
    int b = idx / (Nn * 16);
    int r = idx % (Nn * 16);
    int n = r >> 4, c4 = r & 15;
    float4 v = x4[idx];
    int o4 = n * RowF4 + b * 16 + c4;
    ((__half2*)g_hh)[o4 * 2]     = __floats2half2_rn(v.x, v.y);
    ((__half2*)g_hh)[o4 * 2 + 1] = __floats2half2_rn(v.z, v.w);
}

// -------- SpMM fp16, dual edge streams (BW-bound, at LTS roofline) --------
template <int PHASE>
__global__ void __launch_bounds__(256) spmm16_kernel() {
    const __half* __restrict__ in = (PHASE == 0) ? g_hh : g_t1h;
    __half* __restrict__ out      = (PHASE == 0) ? g_t1h : g_t2h;
    __shared__ float red[8 * 128];
    int n = blockIdx.x;
    int stream = threadIdx.x >> 7;
    int t = threadIdx.x & 127;
    int e0 = g_off[n], e1 = g_off[n + 1];
    float acc[8];
    #pragma unroll
    for (int q = 0; q < 8; ++q) acc[q] = 0.f;
    #pragma unroll 4
    for (int e = e0 + stream; e < e1; e += 2) {
        int   s  = __ldg(&g_csrc[e]);
        float wv = __ldg(&g_csw[e]);
        uint4 raw = __ldg((const uint4*)(in + (size_t)s * RowF) + t);
        const __half2* hp = (const __half2*)&raw;
        #pragma unroll
        for (int p = 0; p < 4; ++p) {
            float2 f = __half22float2(hp[p]);
            acc[2 * p]     = fmaf(wv, f.x, acc[2 * p]);
            acc[2 * p + 1] = fmaf(wv, f.y, acc[2 * p + 1]);
        }
    }
    if (stream) {
        #pragma unroll
        for (int q = 0; q < 8; ++q) red[q * 128 + t] = acc[q];
    }
    __syncthreads();
    if (!stream) {
        uint4 res;
        __half2* rp = (__half2*)&res;
        #pragma unroll
        for (int p = 0; p < 4; ++p)
            rp[p] = __floats2half2_rn(acc[2 * p] + red[(2 * p) * 128 + t],
                                      acc[2 * p + 1] + red[(2 * p + 1) * 128 + t]);
        ((uint4*)(out + (size_t)n * RowF))[t] = res;
    }
}

// -------- merged weight prep (hi only) --------
__device__ __forceinline__ uint32_t pack_f2h(float v0, float v1) {
    __half2 t = __floats2half2_rn(v0, v1);
    return *(uint32_t*)&t;
}
__device__ __forceinline__ float wc_val(const float* __restrict__ cw, int b, int rg, int n) {
    int term = rg >> 6, kk = rg & 63;
    float v;
    if (term == 0)
        v = cw[((size_t)(b * 3 + 0) * 64 + kk) * 128 + n] -
            cw[((size_t)(b * 3 + 2) * 64 + kk) * 128 + n];
    else if (term == 1)
        v = cw[((size_t)(b * 3 + 1) * 64 + kk) * 128 + n];
    else
        v = 2.f * cw[((size_t)(b * 3 + 2) * 64 + kk) * 128 + n];
    return v;
}
__global__ void prep_all(const float* __restrict__ cw,
                         const float* __restrict__ w1,
                         const float* __restrict__ w2) {
    int idx = blockIdx.x * 256 + threadIdx.x;     // 73728 total
    if (idx < 36864) {                            // g_Bc
        int b = idx / 12288, r2 = idx % 12288;
        int c = r2 >> 12, r = r2 & 4095;
        int k2 = r >> 7, t = r & 127;
        int gq = t >> 4, rem = t & 15, wn = rem >> 2, ni = rem & 3;
        int n = wn * 32 + ni * 8 + gq;
        float v0 = wc_val(cw, b, c * 64 + 2 * k2,     n);
        float v1 = wc_val(cw, b, c * 64 + 2 * k2 + 1, n);
        g_Bc[b][c][r] = pack_f2h(v0, v1);
    } else if (idx < 61440) {                     // g_B1
        int j = idx - 36864;
        int b = j / 8192, r2 = j % 8192;
        int c = r2 >> 12, r = r2 & 4095;
        int k2 = r >> 7, t = r & 127;
        int gq = t >> 4, rem = t & 15, wn = rem >> 2, ni = rem & 3;
        int n = wn * 32 + ni * 8 + gq;
        const float* W = w1 + (size_t)b * 16384 + (size_t)c * 64 * 128;
        g_B1[b][c][r] = pack_f2h(W[(size_t)(2 * k2) * 128 + n],
                                 W[(size_t)(2 * k2 + 1) * 128 + n]);
    } else if (idx < 73728) {                     // g_B2
        int j = idx - 61440;
        int b = j / 4096, r2 = j % 4096;
        int c = r2 >> 11, r = r2 & 2047;
        int k2 = r >> 6, t = r & 63;
        int gq = t >> 3, rem = t & 7, wn = rem >> 1, ni = rem & 1;
        int n = wn * 16 + ni * 8 + gq;
        const float* W = w2 + (size_t)b * 8192 + (size_t)c * 64 * 64;
        g_B2[b][c][r] = pack_f2h(W[(size_t)(2 * k2) * 64 + n],
                                 W[(size_t)(2 * k2 + 1) * 64 + n]);
    }
}

// ================== fused GEMM chain (mma.sync f16, single-term) ==================
__device__ __forceinline__ uint32_t s2u(const void* p) {
    uint32_t a;
    asm("{ .reg .u64 t; cvta.to.shared.u64 t, %1; cvt.u32.u64 %0, t; }" : "=r"(a) : "l"(p));
    return a;
}
__device__ __forceinline__ void mma_f16(float* c, const uint32_t* a, const uint32_t* b) {
    asm volatile(
        "mma.sync.aligned.m16n8k16.row.col.f32.f16.f16.f32 "
        "{%0,%1,%2,%3}, {%4,%5,%6,%7}, {%8,%9}, {%0,%1,%2,%3};\n"
        : "+f"(c[0]), "+f"(c[1]), "+f"(c[2]), "+f"(c[3])
        : "r"(a[0]), "r"(a[1]), "r"(a[2]), "r"(a[3]), "r"(b[0]), "r"(b[1]));
}
#define LDSM4(r, a) \
    asm volatile("ldmatrix.sync.aligned.m8n8.x4.shared.b16 {%0,%1,%2,%3}, [%4];" \
        : "=r"((r)[0]), "=r"((r)[1]), "=r"((r)[2]), "=r"((r)[3]) : "r"(a))

__device__ __forceinline__ float swish_t(float v, float sp2, float A) {
    float t;
    asm("tanh.approx.f32 %0, %1;" : "=f"(t) : "f"(v * sp2));
    float va = v * A;
    return fmaf(va, t, va);
}

constexpr int PAH = 136;                 // A tile pitch in halfs
constexpr uint32_t A0_OFF = 0;           // ping buffer
constexpr uint32_t A1_OFF = 34816;       // pong buffer (128*136*2)
constexpr int SMEM_FUSED = 69632;

template <int NI>
__device__ __forceinline__ void mma_chunk(
    uint32_t aLane, int colOffHalfs,
    const uint32_t* __restrict__ BH,
    int wn, int gq, int l4, float acc[4][NI][4])
{
    #pragma unroll
    for (int s = 0; s < 4; ++s) {
        const int k2a = 8 * s + l4, k2b = k2a + 4;
        uint32_t bh[NI][2];
        if constexpr (NI == 4) {
            const int base = gq * 16 + wn * 4;
            uint4 h0 = __ldg((const uint4*)(BH + k2a * 128 + base));
            uint4 h1 = __ldg((const uint4*)(BH + k2b * 128 + base));
            bh[0][0] = h0.x; bh[1][0] = h0.y; bh[2][0] = h0.z; bh[3][0] = h0.w;
            bh[0][1] = h1.x; bh[1][1] = h1.y; bh[2][1] = h1.z; bh[3][1] = h1.w;
        } else {
            const int base = gq * 8 + wn * 2;
            uint2 h0 = __ldg((const uint2*)(BH + k2a * 64 + base));
            uint2 h1 = __ldg((const uint2*)(BH + k2b * 64 + base));
            bh[0][0] = h0.x; bh[1][0] = h0.y;
            bh[0][1] = h1.x; bh[1][1] = h1.y;
        }
        const uint32_t aoff = (uint32_t)(colOffHalfs + s * 16) * 2;
        #pragma unroll
        for (int mi = 0; mi < 4; ++mi) {
            uint32_t ah[4];
            LDSM4(ah, aLane + aoff + mi * (16 * PAH * 2));
            #pragma unroll
            for (int ni = 0; ni < NI; ++ni)
                mma_f16(acc[mi][ni], ah, bh[ni]);
        }
    }
}

__device__ __forceinline__ void fill_A(const __half* __restrict__ srcA, int mblk,
                                       char* smem, uint32_t dstOff, int tid)
{
    for (int i = tid; i < 128 * 8; i += 256) {
        int m = i >> 3, q = i & 7;
        uint4 v = *(const uint4*)(srcA + (size_t)(mblk + m) * 64 + q * 8);
        *(uint4*)(smem + dstOff + (m * PAH + q * 8) * 2) = v;
    }
}

// -------- fused per-block kernel --------
__global__ void __launch_bounds__(256, 2)
fused_block(int first, int last, const float* __restrict__ xin, float* __restrict__ outp,
            const float* __restrict__ b1, const float* __restrict__ b2,
            const float* __restrict__ cb, const float* __restrict__ betaPtr, int blk)
{
    extern __shared__ __align__(16) char smem[];
    const uint32_t sb = s2u(smem);

    const int tid  = threadIdx.x;
    const int warp = tid >> 5, lane = tid & 31;
    const int gq   = lane >> 2, l4 = lane & 3;
    const int wm   = warp >> 2, wn = warp & 3;    // 2 x 4 warp grid
    const int m0w  = wm * 64;
    const int mblk = blockIdx.x * 128;
    const float spv = log1pf(__expf(*betaPtr));
    const float sp2 = 0.5f * spv;
    const float Asw = 1.f / 2.2f;
    const int n0w4 = wn * 32;
    const int n0w2 = wn * 16;

    const uint32_t aLaneOff = (uint32_t)((m0w + (lane & 15)) * PAH + (lane >> 4) * 8) * 2;
    const uint32_t aLane0 = sb + A0_OFF + aLaneOff;
    const uint32_t aLane1 = sb + A1_OFF + aLaneOff;

    // hoisted bias fragments
    float cbv[4][2], b1v[4][2], b2v[2][2];
    #pragma unroll
    for (int ni = 0; ni < 4; ++ni) {
        int c = n0w4 + ni * 8 + 2 * l4;
        float2 t0 = *(const float2*)(cb + c);  cbv[ni][0] = t0.x; cbv[ni][1] = t0.y;
        float2 t1 = *(const float2*)(b1 + c);  b1v[ni][0] = t1.x; b1v[ni][1] = t1.y;
    }
    #pragma unroll
    for (int ni = 0; ni < 2; ++ni) {
        int c = n0w2 + ni * 8 + 2 * l4;
        float2 t2 = *(const float2*)(b2 + c);  b2v[ni][0] = t2.x; b2v[ni][1] = t2.y;
    }

    float acc[4][4][4];

    // ===== Stage 1: cheb, software-pipelined fills over ping-pong buffers =====
    #pragma unroll
    for (int mi = 0; mi < 4; ++mi)
        #pragma unroll
        for (int ni = 0; ni < 4; ++ni)
            #pragma unroll
            for (int q = 0; q < 4; ++q) acc[mi][ni][q] = 0.f;

    fill_A(g_hh, mblk, smem, A0_OFF, tid);                 // ch0 -> A0
    __syncthreads();
    fill_A(g_t1h, mblk, smem, A1_OFF, tid);                // ch1 -> A1 (overlaps mma ch0)
    mma_chunk<4>(aLane0, 0, &g_Bc[blk][0][0], wn, gq, l4, acc);
    __syncthreads();
    fill_A(g_t2h, mblk, smem, A0_OFF, tid);                // ch2 -> A0 (overlaps mma ch1)
    mma_chunk<4>(aLane1, 0, &g_Bc[blk][1][0], wn, gq, l4, acc);
    __syncthreads();
    mma_chunk<4>(aLane0, 0, &g_Bc[blk][2][0], wn, gq, l4, acc);

    // ===== Epilogue 1: bias + swish -> A1 =====
    #pragma unroll
    for (int mi = 0; mi < 4; ++mi) {
        int r0 = m0w + mi * 16 + gq;
        #pragma unroll
        for (int ni = 0; ni < 4; ++ni) {
            int c = n0w4 + ni * 8 + 2 * l4;
            float v00 = swish_t(acc[mi][ni][0] + cbv[ni][0], sp2, Asw);
            float v01 = swish_t(acc[mi][ni][1] + cbv[ni][1], sp2, Asw);
            float v10 = swish_t(acc[mi][ni][2] + cbv[ni][0], sp2, Asw);
            float v11 = swish_t(acc[mi][ni][3] + cbv[ni][1], sp2, Asw);
            *(__half2*)(smem + A1_OFF + (r0 * PAH + c) * 2)       = __floats2half2_rn(v00, v01);
            *(__half2*)(smem + A1_OFF + ((r0 + 8) * PAH + c) * 2) = __floats2half2_rn(v10, v11);
        }
    }
    __syncthreads();

    // ===== Stage 2: MLP1 (K=128 from A1) =====
    #pragma unroll
    for (int mi = 0; mi < 4; ++mi)
        #pragma unroll
        for (int ni = 0; ni < 4; ++ni)
            #pragma unroll
            for (int q = 0; q < 4; ++q) acc[mi][ni][q] = 0.f;

    mma_chunk<4>(aLane1, 0,  &g_B1[blk][0][0], wn, gq, l4, acc);
    mma_chunk<4>(aLane1, 64, &g_B1[blk][1][0], wn, gq, l4, acc);

    // ===== Epilogue 2 -> A0 =====
    #pragma unroll
    for (int mi = 0; mi < 4; ++mi) {
        int r0 = m0w + mi * 16 + gq;
        #pragma unroll
        for (int ni = 0; ni < 4; ++ni) {
            int c = n0w4 + ni * 8 + 2 * l4;
            float v00 = swish_t(acc[mi][ni][0] + b1v[ni][0], sp2, Asw);
            float v01 = swish_t(acc[mi][ni][1] + b1v[ni][1], sp2, Asw);
            float v10 = swish_t(acc[mi][ni][2] + b1v[ni][0], sp2, Asw);
            float v11 = swish_t(acc[mi][ni][3] + b1v[ni][1], sp2, Asw);
            *(__half2*)(smem + A0_OFF + (r0 * PAH + c) * 2)       = __floats2half2_rn(v00, v01);
            *(__half2*)(smem + A0_OFF + ((r0 + 8) * PAH + c) * 2) = __floats2half2_rn(v10, v11);
        }
    }
    __syncthreads();

    // ===== Stage 3: MLP2 (N=64 from A0) + residual (prefetched) =====
    float acc3[4][2][4];
    #pragma unroll
    for (int mi = 0; mi < 4; ++mi)
        #pragma unroll
        for (int ni = 0; ni < 2; ++ni)
            #pragma unroll
            for (int q = 0; q < 4; ++q) acc3[mi][ni][q] = 0.f;

    mma_chunk<2>(aLane0, 0,  &g_B2[blk][0][0], wn, gq, l4, acc3);

    // prefetch residual under the second mma chunk (from x on block 0, else g_h)
    float2 res0[4][2], res1[4][2];
    #pragma unroll
    for (int mi = 0; mi < 4; ++mi) {
        int r0 = mblk + m0w + mi * 16 + gq;
        int r1 = r0 + 8;
        #pragma unroll
        for (int ni = 0; ni < 2; ++ni) {
            int c = n0w2 + ni * 8 + 2 * l4;
            if (first) {
                size_t o0 = (size_t)(r0 & 15) * (Nn * 64) + (size_t)(r0 >> 4) * 64 + c;
                size_t o1 = (size_t)(r1 & 15) * (Nn * 64) + (size_t)(r1 >> 4) * 64 + c;
                res0[mi][ni] = __ldg((const float2*)(xin + o0));
                res1[mi][ni] = __ldg((const float2*)(xin + o1));
            } else {
                res0[mi][ni] = __ldg((const float2*)(g_h + (size_t)r0 * 64 + c));
                res1[mi][ni] = __ldg((const float2*)(g_h + (size_t)r1 * 64 + c));
            }
        }
    }

    mma_chunk<2>(aLane0, 64, &g_B2[blk][1][0], wn, gq, l4, acc3);

    // ===== Final epilogue =====
    #pragma unroll
    for (int mi = 0; mi < 4; ++mi) {
        int r0 = mblk + m0w + mi * 16 + gq;
        #pragma unroll
        for (int ni = 0; ni < 2; ++ni) {
            int c = n0w2 + ni * 8 + 2 * l4;
            float2 cur0 = res0[mi][ni];
            float2 cur1 = res1[mi][ni];
            cur0.x += acc3[mi][ni][0] + b2v[ni][0];
            cur0.y += acc3[mi][ni][1] + b2v[ni][1];
            cur1.x += acc3[mi][ni][2] + b2v[ni][0];
            cur1.y += acc3[mi][ni][3] + b2v[ni][1];
            if (last) {
                int r1 = r0 + 8;
                size_t o0 = (size_t)(r0 & 15) * (Nn * 64) + (size_t)(r0 >> 4) * 64 + c;
                size_t o1 = (size_t)(r1 & 15) * (Nn * 64) + (size_t)(r1 >> 4) * 64 + c;
                *(float2*)(outp + o0) = cur0;
                *(float2*)(outp + o1) = cur1;
            } else {
                *(float2*)(g_h + (size_t)r0 * 64 + c)       = cur0;
                *(float2*)(g_h + (size_t)(r0 + 8) * 64 + c) = cur1;
                *(__half2*)(g_hh + (size_t)r0 * 64 + c)       = __floats2half2_rn(cur0.x, cur0.y);
                *(__half2*)(g_hh + (size_t)(r0 + 8) * 64 + c) = __floats2half2_rn(cur1.x, cur1.y);
            }
        }
    }
}

// -------- host launcher --------
extern "C" void kernel_launch(void* const* d_in, const int* in_sizes, int n_in,
                              void* d_out, int out_size) {
    const float* x      = (const float*)d_in[0];
    const int*   ei     = (const int*)  d_in[1];
    const float* ew     = (const float*)d_in[2];
    const float* cheb_w = (const float*)d_in[3];
    const float* cheb_b = (const float*)d_in[4];
    const float* beta   = (const float*)d_in[5];
    const float* w1     = (const float*)d_in[6];
    const float* b1     = (const float*)d_in[7];
    const float* w2     = (const float*)d_in[8];
    const float* b2     = (const float*)d_in[9];
    float* out = (float*)d_out;
    const int* src = ei;
    const int* dst = ei + Ee;

    cudaFuncSetAttribute((const void*)fused_block,
                         cudaFuncAttributeMaxDynamicSharedMemorySize, SMEM_FUSED);

    const int EB = (Ee + 255) / 256;

    zero_deg_cnt<<<NSCAN, 256>>>();
    deg_cnt_kernel<<<EB, 256>>>(src, dst, ew);
    scan1_kernel<<<NSCAN, 256>>>();
    scan2_kernel<<<1, 128>>>();
    scan3_kernel<<<NSCAN, 256>>>();
    fill_kernel<<<EB, 256>>>(src, dst, ew);
    prep_all<<<288, 256>>>(cheb_w, w1, w2);

    t_in_kernel<<<Nn, 256>>>((const float4*)x);

    for (int b = 0; b < NBlk; ++b) {
        spmm16_kernel<0><<<Nn, 256>>>();
        spmm16_kernel<1><<<Nn, 256>>>();
        fused_block<<<2500, 256, SMEM_FUSED>>>(
            (b == 0) ? 1 : 0, (b == NBlk - 1) ? 1 : 0, x, out,
            b1 + b * 128, b2 + b * 64, cheb_b + b * 128, beta + b, b);
    }
}

// round 17
// speedup vs baseline: 1.0090x; 1.0090x over previous
#include <cuda_runtime.h>
#include <cuda_fp16.h>
#include <stdint.h>
#include <math.h>

// Problem constants
constexpr int Bc   = 16;
constexpr int Nn   = 20000;
constexpr int Cc   = 64;
constexpr int Ee   = 640000;
constexpr int NBlk = 3;
constexpr int ROWS = Nn * Bc;          // 320000
constexpr int RowF = Bc * Cc;          // 1024 halfs per node row ([N][B][C])
constexpr int RowF4 = RowF / 4;
constexpr int NSCAN = (Nn + 255) / 256;  // 79 scan blocks

// -------- device scratch --------
__device__ __align__(16) float  g_h  [ROWS * Cc];
__device__ __align__(16) __half g_hh [ROWS * Cc];
__device__ __align__(16) __half g_t1h[ROWS * Cc];
__device__ __align__(16) __half g_t2h[ROWS * Cc];
__device__ float g_deg [Nn];
__device__ int   g_off [Nn + 1];
__device__ int   g_cnt [Nn];
__device__ int   g_bsum[NSCAN];
__device__ int   g_bbase[NSCAN + 1];
__device__ int   g_csrc[Ee];
__device__ float g_csw [Ee];
// Pre-packed fp16 B operands (hi only), LANE-VECTORIZED fragment layout:
// N=128: word r = k2*128 + gq*16 + wn*4 + ni  (n = wn*32 + ni*8 + gq)
// N=64 : word r = k2*64  + gq*8  + wn*2 + ni  (n = wn*16 + ni*8 + gq)
__device__ __align__(16) uint32_t g_Bc[3][3][32 * 128];   // [block][chunk]
__device__ __align__(16) uint32_t g_B1[3][2][32 * 128];
__device__ __align__(16) uint32_t g_B2[3][2][32 * 64];

// -------- setup kernels --------
__global__ void zero_deg_cnt() {
    int i = blockIdx.x * blockDim.x + threadIdx.x;
    if (i < Nn) { g_deg[i] = 0.f; g_cnt[i] = 0; }
}
// degree accumulate + dst count in one E-pass
__global__ void deg_cnt_kernel(const int* __restrict__ src, const int* __restrict__ dst,
                               const float* __restrict__ ew) {
    int e = blockIdx.x * blockDim.x + threadIdx.x;
    if (e < Ee) {
        atomicAdd(&g_deg[src[e]], ew[e]);
        atomicAdd(&g_cnt[dst[e]], 1);
    }
}
__global__ void scan1_kernel() {
    __shared__ int wsum[8];
    int b = blockIdx.x, t = threadIdx.x;
    int i = b * 256 + t;
    int v = (i < Nn) ? g_cnt[i] : 0;
    if (i < Nn) g_cnt[i] = 0;
    int x = v;
    #pragma unroll
    for (int d = 1; d < 32; d <<= 1) {
        int y = __shfl_up_sync(0xFFFFFFFFu, x, d);
        if ((t & 31) >= d) x += y;
    }
    if ((t & 31) == 31) wsum[t >> 5] = x;
    __syncthreads();
    if (t < 8) {
        int y = wsum[t];
        #pragma unroll
        for (int d = 1; d < 8; d <<= 1) {
            int z = __shfl_up_sync(0xFFu, y, d);
            if (t >= d) y += z;
        }
        wsum[t] = y;
    }
    __syncthreads();
    int excl = (x - v) + ((t >= 32) ? wsum[(t >> 5) - 1] : 0);
    if (i < Nn) g_off[i] = excl;
    if (t == 255) g_bsum[b] = excl + v;
}
__global__ void scan2_kernel() {
    int t = threadIdx.x;
    __shared__ int sh[NSCAN];
    if (t < NSCAN) sh[t] = g_bsum[t];
    __syncthreads();
    if (t == 0) {
        int run = 0;
        #pragma unroll 4
        for (int b = 0; b < NSCAN; ++b) { g_bbase[b] = run; run += sh[b]; }
        g_bbase[NSCAN] = run;
        g_off[Nn] = run;
    }
}
__global__ void scan3_kernel() {
    int i = blockIdx.x * 256 + threadIdx.x;
    if (i < Nn) g_off[i] += g_bbase[blockIdx.x];
}
// fill with inline normalized-weight computation
__global__ void fill_kernel(const int* __restrict__ src, const int* __restrict__ dst,
                            const float* __restrict__ ew) {
    int e = blockIdx.x * blockDim.x + threadIdx.x;
    if (e < Ee) {
        int s = src[e], d = dst[e];
        float ds = g_deg[s], dd = g_deg[d];
        float is = (ds > 0.f) ? rsqrtf(fmaxf(ds, 1e-12f)) : 0.f;
        float id = (dd > 0.f) ? rsqrtf(fmaxf(dd, 1e-12f)) : 0.f;
        int pos = g_off[d] + atomicAdd(&g_cnt[d], 1);
        g_csrc[pos] = s;
        g_csw[pos]  = -is * ew[e] * id;
    }
}

// -------- input transpose (fp32 + fp16 shadow) --------
__global__ void t_in_kernel(const float4* __restrict__ x4) {
    int idx = blockIdx.x * 256 + threadIdx.x;
    int b = idx / (Nn * 16);
    int r = idx % (Nn * 16);
    int n = r >> 4, c4 = r & 15;
    float4 v = x4[idx];
    int o4 = n * RowF4 + b * 16 + c4;
    ((float4*)g_h)[o4] = v;
    ((__half2*)g_hh)[o4 * 2]     = __floats2half2_rn(v.x, v.y);
    ((__half2*)g_hh)[o4 * 2 + 1] = __floats2half2_rn(v.z, v.w);
}

// -------- SpMM fp16, dual edge streams (BW-bound, at LTS roofline) --------
template <int PHASE>
__global__ void __launch_bounds__(256) spmm16_kernel() {
    const __half* __restrict__ in = (PHASE == 0) ? g_hh : g_t1h;
    __half* __restrict__ out      = (PHASE == 0) ? g_t1h : g_t2h;
    __shared__ float red[8 * 128];
    int n = blockIdx.x;
    int stream = threadIdx.x >> 7;
    int t = threadIdx.x & 127;
    int e0 = g_off[n], e1 = g_off[n + 1];
    float acc[8];
    #pragma unroll
    for (int q = 0; q < 8; ++q) acc[q] = 0.f;
    #pragma unroll 4
    for (int e = e0 + stream; e < e1; e += 2) {
        int   s  = __ldg(&g_csrc[e]);
        float wv = __ldg(&g_csw[e]);
        uint4 raw = __ldg((const uint4*)(in + (size_t)s * RowF) + t);
        const __half2* hp = (const __half2*)&raw;
        #pragma unroll
        for (int p = 0; p < 4; ++p) {
            float2 f = __half22float2(hp[p]);
            acc[2 * p]     = fmaf(wv, f.x, acc[2 * p]);
            acc[2 * p + 1] = fmaf(wv, f.y, acc[2 * p + 1]);
        }
    }
    if (stream) {
        #pragma unroll
        for (int q = 0; q < 8; ++q) red[q * 128 + t] = acc[q];
    }
    __syncthreads();
    if (!stream) {
        uint4 res;
        __half2* rp = (__half2*)&res;
        #pragma unroll
        for (int p = 0; p < 4; ++p)
            rp[p] = __floats2half2_rn(acc[2 * p] + red[(2 * p) * 128 + t],
                                      acc[2 * p + 1] + red[(2 * p + 1) * 128 + t]);
        ((uint4*)(out + (size_t)n * RowF))[t] = res;
    }
}

// -------- merged weight prep (hi only) --------
__device__ __forceinline__ uint32_t pack_f2h(float v0, float v1) {
    __half2 t = __floats2half2_rn(v0, v1);
    return *(uint32_t*)&t;
}
__device__ __forceinline__ float wc_val(const float* __restrict__ cw, int b, int rg, int n) {
    int term = rg >> 6, kk = rg & 63;
    float v;
    if (term == 0)
        v = cw[((size_t)(b * 3 + 0) * 64 + kk) * 128 + n] -
            cw[((size_t)(b * 3 + 2) * 64 + kk) * 128 + n];
    else if (term == 1)
        v = cw[((size_t)(b * 3 + 1) * 64 + kk) * 128 + n];
    else
        v = 2.f * cw[((size_t)(b * 3 + 2) * 64 + kk) * 128 + n];
    return v;
}
__global__ void prep_all(const float* __restrict__ cw,
                         const float* __restrict__ w1,
                         const float* __restrict__ w2) {
    int idx = blockIdx.x * 256 + threadIdx.x;     // 73728 total
    if (idx < 36864) {                            // g_Bc
        int b = idx / 12288, r2 = idx % 12288;
        int c = r2 >> 12, r = r2 & 4095;
        int k2 = r >> 7, t = r & 127;
        int gq = t >> 4, rem = t & 15, wn = rem >> 2, ni = rem & 3;
        int n = wn * 32 + ni * 8 + gq;
        float v0 = wc_val(cw, b, c * 64 + 2 * k2,     n);
        float v1 = wc_val(cw, b, c * 64 + 2 * k2 + 1, n);
        g_Bc[b][c][r] = pack_f2h(v0, v1);
    } else if (idx < 61440) {                     // g_B1
        int j = idx - 36864;
        int b = j / 8192, r2 = j % 8192;
        int c = r2 >> 12, r = r2 & 4095;
        int k2 = r >> 7, t = r & 127;
        int gq = t >> 4, rem = t & 15, wn = rem >> 2, ni = rem & 3;
        int n = wn * 32 + ni * 8 + gq;
        const float* W = w1 + (size_t)b * 16384 + (size_t)c * 64 * 128;
        g_B1[b][c][r] = pack_f2h(W[(size_t)(2 * k2) * 128 + n],
                                 W[(size_t)(2 * k2 + 1) * 128 + n]);
    } else if (idx < 73728) {                     // g_B2
        int j = idx - 61440;
        int b = j / 4096, r2 = j % 4096;
        int c = r2 >> 11, r = r2 & 2047;
        int k2 = r >> 6, t = r & 63;
        int gq = t >> 3, rem = t & 7, wn = rem >> 1, ni = rem & 1;
        int n = wn * 16 + ni * 8 + gq;
        const float* W = w2 + (size_t)b * 8192 + (size_t)c * 64 * 64;
        g_B2[b][c][r] = pack_f2h(W[(size_t)(2 * k2) * 64 + n],
                                 W[(size_t)(2 * k2 + 1) * 64 + n]);
    }
}

// ================== fused GEMM chain (mma.sync f16, single-term) ==================
__device__ __forceinline__ uint32_t s2u(const void* p) {
    uint32_t a;
    asm("{ .reg .u64 t; cvta.to.shared.u64 t, %1; cvt.u32.u64 %0, t; }" : "=r"(a) : "l"(p));
    return a;
}
__device__ __forceinline__ void mma_f16(float* c, const uint32_t* a, const uint32_t* b) {
    asm volatile(
        "mma.sync.aligned.m16n8k16.row.col.f32.f16.f16.f32 "
        "{%0,%1,%2,%3}, {%4,%5,%6,%7}, {%8,%9}, {%0,%1,%2,%3};\n"
        : "+f"(c[0]), "+f"(c[1]), "+f"(c[2]), "+f"(c[3])
        : "r"(a[0]), "r"(a[1]), "r"(a[2]), "r"(a[3]), "r"(b[0]), "r"(b[1]));
}
#define LDSM4(r, a) \
    asm volatile("ldmatrix.sync.aligned.m8n8.x4.shared.b16 {%0,%1,%2,%3}, [%4];" \
        : "=r"((r)[0]), "=r"((r)[1]), "=r"((r)[2]), "=r"((r)[3]) : "r"(a))

__device__ __forceinline__ float swish_t(float v, float sp2, float A) {
    float t;
    asm("tanh.approx.f32 %0, %1;" : "=f"(t) : "f"(v * sp2));
    float va = v * A;
    return fmaf(va, t, va);
}

constexpr int PAH = 136;                 // A tile pitch in halfs
constexpr uint32_t A0_OFF = 0;           // ping buffer
constexpr uint32_t A1_OFF = 34816;       // pong buffer (128*136*2)
constexpr int SMEM_FUSED = 69632;

template <int NI>
__device__ __forceinline__ void mma_chunk(
    uint32_t aLane, int colOffHalfs,
    const uint32_t* __restrict__ BH,
    int wn, int gq, int l4, float acc[4][NI][4])
{
    #pragma unroll
    for (int s = 0; s < 4; ++s) {
        const int k2a = 8 * s + l4, k2b = k2a + 4;
        uint32_t bh[NI][2];
        if constexpr (NI == 4) {
            const int base = gq * 16 + wn * 4;
            uint4 h0 = __ldg((const uint4*)(BH + k2a * 128 + base));
            uint4 h1 = __ldg((const uint4*)(BH + k2b * 128 + base));
            bh[0][0] = h0.x; bh[1][0] = h0.y; bh[2][0] = h0.z; bh[3][0] = h0.w;
            bh[0][1] = h1.x; bh[1][1] = h1.y; bh[2][1] = h1.z; bh[3][1] = h1.w;
        } else {
            const int base = gq * 8 + wn * 2;
            uint2 h0 = __ldg((const uint2*)(BH + k2a * 64 + base));
            uint2 h1 = __ldg((const uint2*)(BH + k2b * 64 + base));
            bh[0][0] = h0.x; bh[1][0] = h0.y;
            bh[0][1] = h1.x; bh[1][1] = h1.y;
        }
        const uint32_t aoff = (uint32_t)(colOffHalfs + s * 16) * 2;
        #pragma unroll
        for (int mi = 0; mi < 4; ++mi) {
            uint32_t ah[4];
            LDSM4(ah, aLane + aoff + mi * (16 * PAH * 2));
            #pragma unroll
            for (int ni = 0; ni < NI; ++ni)
                mma_f16(acc[mi][ni], ah, bh[ni]);
        }
    }
}

__device__ __forceinline__ void fill_A(const __half* __restrict__ srcA, int mblk,
                                       char* smem, uint32_t dstOff, int tid)
{
    for (int i = tid; i < 128 * 8; i += 256) {
        int m = i >> 3, q = i & 7;
        uint4 v = *(const uint4*)(srcA + (size_t)(mblk + m) * 64 + q * 8);
        *(uint4*)(smem + dstOff + (m * PAH + q * 8) * 2) = v;
    }
}

// -------- fused per-block kernel --------
__global__ void __launch_bounds__(256, 2)
fused_block(int blk, int last, float* __restrict__ outp,
            const float* __restrict__ b1, const float* __restrict__ b2,
            const float* __restrict__ cb, const float* __restrict__ betaPtr)
{
    extern __shared__ __align__(16) char smem[];
    const uint32_t sb = s2u(smem);

    const int tid  = threadIdx.x;
    const int warp = tid >> 5, lane = tid & 31;
    const int gq   = lane >> 2, l4 = lane & 3;
    const int wm   = warp >> 2, wn = warp & 3;    // 2 x 4 warp grid
    const int m0w  = wm * 64;
    const int mblk = blockIdx.x * 128;
    const float spv = log1pf(__expf(*betaPtr));
    const float sp2 = 0.5f * spv;
    const float Asw = 1.f / 2.2f;
    const int n0w4 = wn * 32;
    const int n0w2 = wn * 16;

    const uint32_t aLaneOff = (uint32_t)((m0w + (lane & 15)) * PAH + (lane >> 4) * 8) * 2;
    const uint32_t aLane0 = sb + A0_OFF + aLaneOff;
    const uint32_t aLane1 = sb + A1_OFF + aLaneOff;

    // hoisted bias fragments
    float cbv[4][2], b1v[4][2], b2v[2][2];
    #pragma unroll
    for (int ni = 0; ni < 4; ++ni) {
        int c = n0w4 + ni * 8 + 2 * l4;
        float2 t0 = *(const float2*)(cb + c);  cbv[ni][0] = t0.x; cbv[ni][1] = t0.y;
        float2 t1 = *(const float2*)(b1 + c);  b1v[ni][0] = t1.x; b1v[ni][1] = t1.y;
    }
    #pragma unroll
    for (int ni = 0; ni < 2; ++ni) {
        int c = n0w2 + ni * 8 + 2 * l4;
        float2 t2 = *(const float2*)(b2 + c);  b2v[ni][0] = t2.x; b2v[ni][1] = t2.y;
    }

    float acc[4][4][4];

    // ===== Stage 1: cheb, software-pipelined fills over ping-pong buffers =====
    #pragma unroll
    for (int mi = 0; mi < 4; ++mi)
        #pragma unroll
        for (int ni = 0; ni < 4; ++ni)
            #pragma unroll
            for (int q = 0; q < 4; ++q) acc[mi][ni][q] = 0.f;

    fill_A(g_hh, mblk, smem, A0_OFF, tid);                 // ch0 -> A0
    __syncthreads();
    fill_A(g_t1h, mblk, smem, A1_OFF, tid);                // ch1 -> A1 (overlaps mma ch0)
    mma_chunk<4>(aLane0, 0, &g_Bc[blk][0][0], wn, gq, l4, acc);
    __syncthreads();
    fill_A(g_t2h, mblk, smem, A0_OFF, tid);                // ch2 -> A0 (overlaps mma ch1)
    mma_chunk<4>(aLane1, 0, &g_Bc[blk][1][0], wn, gq, l4, acc);
    __syncthreads();
    mma_chunk<4>(aLane0, 0, &g_Bc[blk][2][0], wn, gq, l4, acc);

    // ===== Epilogue 1: bias + swish -> A1 =====
    #pragma unroll
    for (int mi = 0; mi < 4; ++mi) {
        int r0 = m0w + mi * 16 + gq;
        #pragma unroll
        for (int ni = 0; ni < 4; ++ni) {
            int c = n0w4 + ni * 8 + 2 * l4;
            float v00 = swish_t(acc[mi][ni][0] + cbv[ni][0], sp2, Asw);
            float v01 = swish_t(acc[mi][ni][1] + cbv[ni][1], sp2, Asw);
            float v10 = swish_t(acc[mi][ni][2] + cbv[ni][0], sp2, Asw);
            float v11 = swish_t(acc[mi][ni][3] + cbv[ni][1], sp2, Asw);
            *(__half2*)(smem + A1_OFF + (r0 * PAH + c) * 2)       = __floats2half2_rn(v00, v01);
            *(__half2*)(smem + A1_OFF + ((r0 + 8) * PAH + c) * 2) = __floats2half2_rn(v10, v11);
        }
    }
    __syncthreads();

    // ===== Stage 2: MLP1 (K=128 from A1) =====
    #pragma unroll
    for (int mi = 0; mi < 4; ++mi)
        #pragma unroll
        for (int ni = 0; ni < 4; ++ni)
            #pragma unroll
            for (int q = 0; q < 4; ++q) acc[mi][ni][q] = 0.f;

    mma_chunk<4>(aLane1, 0,  &g_B1[blk][0][0], wn, gq, l4, acc);
    mma_chunk<4>(aLane1, 64, &g_B1[blk][1][0], wn, gq, l4, acc);

    // ===== Epilogue 2 -> A0 =====
    #pragma unroll
    for (int mi = 0; mi < 4; ++mi) {
        int r0 = m0w + mi * 16 + gq;
        #pragma unroll
        for (int ni = 0; ni < 4; ++ni) {
            int c = n0w4 + ni * 8 + 2 * l4;
            float v00 = swish_t(acc[mi][ni][0] + b1v[ni][0], sp2, Asw);
            float v01 = swish_t(acc[mi][ni][1] + b1v[ni][1], sp2, Asw);
            float v10 = swish_t(acc[mi][ni][2] + b1v[ni][0], sp2, Asw);
            float v11 = swish_t(acc[mi][ni][3] + b1v[ni][1], sp2, Asw);
            *(__half2*)(smem + A0_OFF + (r0 * PAH + c) * 2)       = __floats2half2_rn(v00, v01);
            *(__half2*)(smem + A0_OFF + ((r0 + 8) * PAH + c) * 2) = __floats2half2_rn(v10, v11);
        }
    }
    __syncthreads();

    // ===== Stage 3: MLP2 (N=64 from A0) + residual (prefetched) =====
    float acc3[4][2][4];
    #pragma unroll
    for (int mi = 0; mi < 4; ++mi)
        #pragma unroll
        for (int ni = 0; ni < 2; ++ni)
            #pragma unroll
            for (int q = 0; q < 4; ++q) acc3[mi][ni][q] = 0.f;

    mma_chunk<2>(aLane0, 0,  &g_B2[blk][0][0], wn, gq, l4, acc3);

    // prefetch residual h under the second mma chunk
    float2 res0[4][2], res1[4][2];
    #pragma unroll
    for (int mi = 0; mi < 4; ++mi) {
        int r0 = mblk + m0w + mi * 16 + gq;
        #pragma unroll
        for (int ni = 0; ni < 2; ++ni) {
            int c = n0w2 + ni * 8 + 2 * l4;
            res0[mi][ni] = __ldg((const float2*)(g_h + (size_t)r0 * 64 + c));
            res1[mi][ni] = __ldg((const float2*)(g_h + (size_t)(r0 + 8) * 64 + c));
        }
    }

    mma_chunk<2>(aLane0, 64, &g_B2[blk][1][0], wn, gq, l4, acc3);

    // ===== Final epilogue =====
    #pragma unroll
    for (int mi = 0; mi < 4; ++mi) {
        int r0 = mblk + m0w + mi * 16 + gq;
        #pragma unroll
        for (int ni = 0; ni < 2; ++ni) {
            int c = n0w2 + ni * 8 + 2 * l4;
            float2 cur0 = res0[mi][ni];
            float2 cur1 = res1[mi][ni];
            cur0.x += acc3[mi][ni][0] + b2v[ni][0];
            cur0.y += acc3[mi][ni][1] + b2v[ni][1];
            cur1.x += acc3[mi][ni][2] + b2v[ni][0];
            cur1.y += acc3[mi][ni][3] + b2v[ni][1];
            if (last) {
                int r1 = r0 + 8;
                size_t o0 = (size_t)(r0 & 15) * (Nn * 64) + (size_t)(r0 >> 4) * 64 + c;
                size_t o1 = (size_t)(r1 & 15) * (Nn * 64) + (size_t)(r1 >> 4) * 64 + c;
                *(float2*)(outp + o0) = cur0;
                *(float2*)(outp + o1) = cur1;
            } else {
                *(float2*)(g_h + (size_t)r0 * 64 + c)       = cur0;
                *(float2*)(g_h + (size_t)(r0 + 8) * 64 + c) = cur1;
                *(__half2*)(g_hh + (size_t)r0 * 64 + c)       = __floats2half2_rn(cur0.x, cur0.y);
                *(__half2*)(g_hh + (size_t)(r0 + 8) * 64 + c) = __floats2half2_rn(cur1.x, cur1.y);
            }
        }
    }
}

// -------- host launcher --------
extern "C" void kernel_launch(void* const* d_in, const int* in_sizes, int n_in,
                              void* d_out, int out_size) {
    const float* x      = (const float*)d_in[0];
    const int*   ei     = (const int*)  d_in[1];
    const float* ew     = (const float*)d_in[2];
    const float* cheb_w = (const float*)d_in[3];
    const float* cheb_b = (const float*)d_in[4];
    const float* beta   = (const float*)d_in[5];
    const float* w1     = (const float*)d_in[6];
    const float* b1     = (const float*)d_in[7];
    const float* w2     = (const float*)d_in[8];
    const float* b2     = (const float*)d_in[9];
    float* out = (float*)d_out;
    const int* src = ei;
    const int* dst = ei + Ee;

    cudaFuncSetAttribute((const void*)fused_block,
                         cudaFuncAttributeMaxDynamicSharedMemorySize, SMEM_FUSED);

    const int EB = (Ee + 255) / 256;

    zero_deg_cnt<<<NSCAN, 256>>>();
    deg_cnt_kernel<<<EB, 256>>>(src, dst, ew);
    scan1_kernel<<<NSCAN, 256>>>();
    scan2_kernel<<<1, 128>>>();
    scan3_kernel<<<NSCAN, 256>>>();
    fill_kernel<<<EB, 256>>>(src, dst, ew);
    prep_all<<<288, 256>>>(cheb_w, w1, w2);

    t_in_kernel<<<Nn, 256>>>((const float4*)x);

    for (int b = 0; b < NBlk; ++b) {
        spmm16_kernel<0><<<Nn, 256>>>();
        spmm16_kernel<1><<<Nn, 256>>>();
        fused_block<<<2500, 256, SMEM_FUSED>>>(
            b, (b == NBlk - 1) ? 1 : 0, out,
            b1 + b * 128, b2 + b * 64, cheb_b + b * 128, beta + b);
    }
}